// round 16
// baseline (speedup 1.0000x reference)
#include <cuda_runtime.h>
#include <cuda_bf16.h>

#define NN 1024
#define HID 256
#define NH 8
#define HD 32
#define NE 16384

#define TBL_N 8192
#define TBL_MAX 24.0f
#define TBL_SCALE ((float)(TBL_N - 1) / TBL_MAX)

typedef unsigned long long ull;

// ---- packed fp32x2 helpers (sm_103a FFMA2) ----------------------------------
__device__ __forceinline__ ull pack2(float lo, float hi) {
    ull r; asm("mov.b64 %0, {%1, %2};" : "=l"(r) : "f"(lo), "f"(hi)); return r;
}
__device__ __forceinline__ float2 unpack2(ull v) {
    float2 f; asm("mov.b64 {%0, %1}, %2;" : "=f"(f.x), "=f"(f.y) : "l"(v)); return f;
}
__device__ __forceinline__ void fma2(ull& d, ull a, ull b) {
    asm("fma.rn.f32x2 %0, %1, %2, %0;" : "+l"(d) : "l"(a), "l"(b));
}

// ---------------- scratch (static device memory; no allocations) -------------
__device__ float    g_q[NN * HID];
__device__ float    g_k[NN * HID];
__device__ float    g_v[NN * HID];
__device__ float    g_gateh[NN * 4 * HID];
__device__ float    g_gate[NN * 2];
__device__ unsigned g_adj[NN * 32];
__device__ unsigned g_pa[NN * 32];
__device__ unsigned g_pb[NN * 32];
__device__ float    g_ttab[16];                  // [path_val(0/1)][head]
__device__ float    g_tbl[TBL_N * 8];            // geo MLP lookup table [i][h]
__device__ float    g_logits[NN * NH * NN];      // 32 MB, [n][h][m], raw logits
__device__ float2   g_stats[NN * NH];            // per-row (max, 1/sum)
__device__ float    g_attnout[NN * HID];
__device__ float    g_proj[NN * HID];

// ------- setup: geo table (blocks 0-31) + zero adj slices + ttab (block 32) --
__global__ void setup_kernel(const float* __restrict__ gw1, const float* __restrict__ gb1,
                             const float* __restrict__ gw2, const float* __restrict__ gb2,
                             const float* __restrict__ tw1, const float* __restrict__ tb1,
                             const float* __restrict__ tw2, const float* __restrict__ tb2) {
    int b = blockIdx.x, tid = threadIdx.x;
    if (b < 32) {
#pragma unroll
        for (int t = 0; t < 4; t++) g_adj[b * 1024 + tid + 256 * t] = 0u;
        int i = b * 256 + tid;
        float dist = (float)i * (TBL_MAX / (float)(TBL_N - 1));
        float a[8];
#pragma unroll
        for (int h = 0; h < 8; h++) a[h] = gb2[h];
        for (int c = 0; c < 32; c++) {
            float hv = fmaf(dist, gw1[c], gb1[c]);
            float s = __fdividef(hv, 1.f + __expf(-hv));
#pragma unroll
            for (int h = 0; h < 8; h++) a[h] = fmaf(s, gw2[c * 8 + h], a[h]);
        }
#pragma unroll
        for (int h = 0; h < 8; h++) g_tbl[i * 8 + h] = a[h];
    } else {
        if (tid < 16) {
            float pv = (float)(tid >> 3);
            int h = tid & 7;
            float acc = tb2[h];
            for (int c = 0; c < 32; c++) {
                float hv = fmaf(pv, tw1[c], tb1[c]);
                float s = __fdividef(hv, 1.f + __expf(-hv));
                acc = fmaf(s, tw2[c * 8 + h], acc);
            }
            g_ttab[tid] = acc;
        }
    }
}

// ---------------- scatter edges with inline dtype detect ----------------------
__global__ void scatter_edges_kernel(const unsigned* __restrict__ w) {
    bool is64 = true;
#pragma unroll
    for (int i = 1; i < 16; i += 2) is64 &= (w[i] == 0u);
    int e = blockIdx.x * blockDim.x + threadIdx.x;
    if (e >= NE) return;
    int s, d;
    if (is64) {
        const long long* p = (const long long*)w;
        s = (int)p[e];
        d = (int)p[NE + e];
    } else {
        const int* p = (const int*)w;
        s = p[e];
        d = p[NE + e];
    }
    atomicOr(&g_adj[s * 32 + (d >> 5)], 1u << (d & 31));
}

// path = min(path, path @ adj): binary reachability step on bitsets.
#define LIST_CAP 512
__global__ __launch_bounds__(256) void path_round_kernel(int r) {
    const unsigned* in = (r == 0) ? g_adj : ((r == 1) ? g_pa : g_pb);
    unsigned* out = (r == 1) ? g_pb : g_pa;
    __shared__ unsigned short lists[8][LIST_CAP];
    int warp = threadIdx.x >> 5, lane = threadIdx.x & 31;
    int row = blockIdx.x * 8 + warp;
    unsigned w = in[row * 32 + lane];
    int c = __popc(w);
    int pre = c;
#pragma unroll
    for (int o = 1; o < 32; o <<= 1) {
        int x = __shfl_up_sync(~0u, pre, o);
        if (lane >= o) pre += x;
    }
    int total = __shfl_sync(~0u, pre, 31);
    unsigned acc = 0u;
    if (total <= LIST_CAP) {
        int k = pre - c;
        unsigned tmp = w;
        while (tmp) {
            int b = __ffs(tmp) - 1; tmp &= tmp - 1;
            lists[warp][k++] = (unsigned short)(lane * 32 + b);
        }
        __syncwarp();
        int j = 0;
        for (; j + 8 <= total; j += 8) {
            unsigned a0 = g_adj[lists[warp][j + 0] * 32 + lane];
            unsigned a1 = g_adj[lists[warp][j + 1] * 32 + lane];
            unsigned a2 = g_adj[lists[warp][j + 2] * 32 + lane];
            unsigned a3 = g_adj[lists[warp][j + 3] * 32 + lane];
            unsigned a4 = g_adj[lists[warp][j + 4] * 32 + lane];
            unsigned a5 = g_adj[lists[warp][j + 5] * 32 + lane];
            unsigned a6 = g_adj[lists[warp][j + 6] * 32 + lane];
            unsigned a7 = g_adj[lists[warp][j + 7] * 32 + lane];
            acc |= (a0 | a1) | (a2 | a3) | (a4 | a5) | (a6 | a7);
        }
        for (; j < total; j++) acc |= g_adj[lists[warp][j] * 32 + lane];
    } else {
        for (int ww = 0; ww < 32; ww++) {
            unsigned word = __shfl_sync(~0u, w, ww);
            while (word) {
                int b = __ffs(word) - 1; word &= word - 1;
                acc |= g_adj[(ww * 32 + b) * 32 + lane];
            }
        }
    }
    out[row * 32 + lane] = w & acc;
}

// ---- 64x64 tiled SGEMM body, DOUBLE-BUFFERED + FFMA2 row pairs --------------
// C = [A0|A1] @ B + bias [, silu]. Bit-identical math to scalar version.
__device__ __forceinline__ void gemm_body(
    const float* __restrict__ A0, const float* __restrict__ A1, int ksplit,
    int lda, const float* __restrict__ B, int ldb,
    const float* __restrict__ bias, float* __restrict__ C, int ldc, int K, int act)
{
    __shared__ float As[2][16][68];
    __shared__ float Bs[2][16][64];
    int tid = threadIdx.x;
    int tx = tid & 15, ty = tid >> 4;
    int row0 = blockIdx.y * 64, col0 = blockIdx.x * 64;
    ull acc2[2][4];     // row pairs (ty*4+2p, +1) x cols (tx*4+j)
#pragma unroll
    for (int p = 0; p < 2; p++)
#pragma unroll
        for (int j = 0; j < 4; j++) acc2[p][j] = 0ull;
    int ar = tid >> 2, ac = (tid & 3) << 2;
    int bk = tid >> 4, bn = (tid & 15) << 2;

    // prologue: load k-tile 0 into buffer 0
    {
        const float* Ap = (0 < ksplit)
            ? &A0[(row0 + ar) * lda + ac]
            : &A1[(row0 + ar) * lda + ac];
        float4 av = *(const float4*)Ap;
        As[0][ac + 0][ar] = av.x; As[0][ac + 1][ar] = av.y;
        As[0][ac + 2][ar] = av.z; As[0][ac + 3][ar] = av.w;
        *(float4*)&Bs[0][bk][bn] = *(const float4*)&B[bk * ldb + col0 + bn];
    }
    __syncthreads();

    int cur = 0;
    for (int k0 = 0; k0 < K; k0 += 16) {
        int nxt = cur ^ 1;
        bool has_next = (k0 + 16 < K);
        float4 av, bv;
        if (has_next) {
            int k1 = k0 + 16;
            const float* Ap = (k1 < ksplit)
                ? &A0[(row0 + ar) * lda + k1 + ac]
                : &A1[(row0 + ar) * lda + (k1 - ksplit) + ac];
            av = *(const float4*)Ap;
            bv = *(const float4*)&B[(k1 + bk) * ldb + col0 + bn];
        }
#pragma unroll
        for (int kk = 0; kk < 16; kk++) {
            // rows (ty*4, +1) and (ty*4+2, +3) as packed pairs, single 16B LDS
            ulonglong2 ap = *(const ulonglong2*)&As[cur][kk][ty << 2];
            float4 b = *(const float4*)&Bs[cur][kk][tx << 2];
            ull bb0 = pack2(b.x, b.x), bb1 = pack2(b.y, b.y);
            ull bb2 = pack2(b.z, b.z), bb3 = pack2(b.w, b.w);
            fma2(acc2[0][0], ap.x, bb0); fma2(acc2[0][1], ap.x, bb1);
            fma2(acc2[0][2], ap.x, bb2); fma2(acc2[0][3], ap.x, bb3);
            fma2(acc2[1][0], ap.y, bb0); fma2(acc2[1][1], ap.y, bb1);
            fma2(acc2[1][2], ap.y, bb2); fma2(acc2[1][3], ap.y, bb3);
        }
        if (has_next) {
            As[nxt][ac + 0][ar] = av.x; As[nxt][ac + 1][ar] = av.y;
            As[nxt][ac + 2][ar] = av.z; As[nxt][ac + 3][ar] = av.w;
            *(float4*)&Bs[nxt][bk][bn] = bv;
            __syncthreads();
        }
        cur = nxt;
    }
#pragma unroll
    for (int p = 0; p < 2; p++) {
        int r = row0 + (ty << 2) + (p << 1);
#pragma unroll
        for (int j = 0; j < 4; j++) {
            int cc = col0 + (tx << 2) + j;
            float2 v = unpack2(acc2[p][j]);
            float v0 = v.x + bias[cc];
            float v1 = v.y + bias[cc];
            if (act) {
                v0 = __fdividef(v0, 1.f + __expf(-v0));
                v1 = __fdividef(v1, 1.f + __expf(-v1));
            }
            C[r * ldc + cc] = v0;
            C[(r + 1) * ldc + cc] = v1;
        }
    }
}

__global__ __launch_bounds__(256) void sgemm64(
    const float* __restrict__ A0, const float* __restrict__ A1, int ksplit,
    int lda, const float* __restrict__ B, int ldb,
    const float* __restrict__ bias, float* __restrict__ C, int ldc, int K, int act)
{
    gemm_body(A0, A1, ksplit, lda, B, ldb, bias, C, ldc, K, act);
}

// q/k/v projections fused via blockIdx.z
__global__ __launch_bounds__(256) void qkv_kernel(
    const float* __restrict__ src, const float* __restrict__ tgt,
    const float* __restrict__ Wq, const float* __restrict__ bq,
    const float* __restrict__ Wk, const float* __restrict__ bk,
    const float* __restrict__ Wv, const float* __restrict__ bv)
{
    int z = blockIdx.z;
    const float* A = (z == 0) ? src : tgt;
    const float* W = (z == 0) ? Wq : ((z == 1) ? Wk : Wv);
    const float* b = (z == 0) ? bq : ((z == 1) ? bk : bv);
    float* C = (z == 0) ? g_q : ((z == 1) ? g_k : g_v);
    gemm_body(A, A, 256, 256, W, 256, b, C, 256, 256, 0);
}

// gate logits: 2 dots of length 1024 per node, then 2-way softmax
__global__ __launch_bounds__(256) void gate2_kernel(const float* __restrict__ w2,
                                                    const float* __restrict__ b2) {
    int n = blockIdx.x, tid = threadIdx.x;
    const float* hrow = g_gateh + n * 1024;
    float s0 = 0.f, s1 = 0.f;
#pragma unroll
    for (int t = 0; t < 4; t++) {
        int j = tid + 256 * t;
        float hv = hrow[j];
        s0 = fmaf(hv, w2[j * 2 + 0], s0);
        s1 = fmaf(hv, w2[j * 2 + 1], s1);
    }
    for (int o = 16; o; o >>= 1) {
        s0 += __shfl_xor_sync(~0u, s0, o);
        s1 += __shfl_xor_sync(~0u, s1, o);
    }
    __shared__ float r0[8], r1[8];
    if ((tid & 31) == 0) { r0[tid >> 5] = s0; r1[tid >> 5] = s1; }
    __syncthreads();
    if (tid == 0) {
        float l0 = b2[0], l1 = b2[1];
        for (int j = 0; j < 8; j++) { l0 += r0[j]; l1 += r1[j]; }
        float m = fmaxf(l0, l1);
        float e0 = __expf(l0 - m), e1 = __expf(l1 - m);
        float inv = __fdividef(1.f, e0 + e1);
        g_gate[n * 2 + 0] = e0 * inv;
        g_gate[n * 2 + 1] = e1 * inv;
    }
}

// ======== logits: 64n x 32m tile, thread = 4n x 2m x 4h, 2 head-groups =======
#define LQ_QS   0                       // [64][132]
#define LQ_KS   8448                    // [32][132]
#define LQ_SPN  12672                   // 192
#define LQ_SPM  12864                   // 96
#define LQ_SG0  12960                   // 64
#define LQ_SG1  13024                   // 64
#define LQ_STT  13088                   // 16
#define LQ_SPW  13104                   // 64 (unsigned)
#define LOGITS_SMEM ((13104 + 64) * 4)

__global__ __launch_bounds__(256) void logits_kernel(const float* __restrict__ pos)
{
    extern __shared__ float sh[];
    float* qs = sh + LQ_QS;
    float* ks = sh + LQ_KS;
    float* spn = sh + LQ_SPN;
    float* spm = sh + LQ_SPM;
    float* sg0 = sh + LQ_SG0;
    float* sg1 = sh + LQ_SG1;
    float* stt = sh + LQ_STT;
    unsigned* spw = (unsigned*)(sh + LQ_SPW);

    int tid = threadIdx.x;
    int tx = tid & 15, ty = tid >> 4;
    int m0 = blockIdx.x * 32, n0 = blockIdx.y * 64;
    const float scale = 0.17677669529663687f;   // 1/sqrt(32)

    if (tid < 192) spn[tid] = pos[n0 * 3 + tid];
    if (tid < 96)  spm[tid] = pos[m0 * 3 + tid];
    if (tid < 64) {
        sg0[tid] = g_gate[(n0 + tid) * 2 + 0];
        sg1[tid] = g_gate[(n0 + tid) * 2 + 1];
        spw[tid] = g_pa[(n0 + tid) * 32 + (m0 >> 5)];
    }
    if (tid < 16) stt[tid] = g_ttab[tid];
    __syncthreads();

    int i0r[8]; float frr[8]; unsigned bitm = 0;
#pragma unroll
    for (int i = 0; i < 4; i++) {
        int n = ty * 4 + i;
        float pnx = spn[n * 3 + 0], pny = spn[n * 3 + 1], pnz = spn[n * 3 + 2];
#pragma unroll
        for (int j = 0; j < 2; j++) {
            int m = tx + 16 * j;
            float dx = pnx - spm[m * 3 + 0];
            float dy = pny - spm[m * 3 + 1];
            float dz = pnz - spm[m * 3 + 2];
            float dist = sqrtf(fmaxf(dx * dx + dy * dy + dz * dz, 1e-12f));
            float t = fminf(dist, TBL_MAX) * TBL_SCALE;
            int i0 = (int)t;
            if (i0 > TBL_N - 2) i0 = TBL_N - 2;
            int p = i * 2 + j;
            i0r[p] = i0;
            frr[p] = t - (float)i0;
            bitm |= ((spw[n] >> m) & 1u) << p;
        }
    }

    for (int g = 0; g < 2; g++) {
        __syncthreads();
        for (int l = tid; l < 2048; l += 256) {
            int r = l >> 5, c4 = (l & 31) << 2;
            *(float4*)&qs[r * 132 + c4] =
                *(const float4*)&g_q[(n0 + r) * 256 + g * 128 + c4];
        }
        for (int l = tid; l < 1024; l += 256) {
            int r = l >> 5, c4 = (l & 31) << 2;
            *(float4*)&ks[r * 132 + c4] =
                *(const float4*)&g_k[(m0 + r) * 256 + g * 128 + c4];
        }
        __syncthreads();

        float res[4][4][2];
#pragma unroll
        for (int hh = 0; hh < 4; hh++)
#pragma unroll
            for (int i = 0; i < 4; i++) { res[hh][i][0] = 0.f; res[hh][i][1] = 0.f; }

#pragma unroll
        for (int dd = 0; dd < 128; dd += 4) {
            const int hh = dd >> 5;
            float4 qv[4], kv[2];
#pragma unroll
            for (int i = 0; i < 4; i++)
                qv[i] = *(const float4*)&qs[(ty * 4 + i) * 132 + dd];
            kv[0] = *(const float4*)&ks[tx * 132 + dd];
            kv[1] = *(const float4*)&ks[(tx + 16) * 132 + dd];
#pragma unroll
            for (int i = 0; i < 4; i++) {
#pragma unroll
                for (int j = 0; j < 2; j++) {
                    res[hh][i][j] = fmaf(qv[i].x, kv[j].x,
                                    fmaf(qv[i].y, kv[j].y,
                                    fmaf(qv[i].z, kv[j].z,
                                    fmaf(qv[i].w, kv[j].w, res[hh][i][j]))));
                }
            }
        }

        float tt0[4], tt1[4];
#pragma unroll
        for (int hh = 0; hh < 4; hh++) {
            tt0[hh] = stt[4 * g + hh];
            tt1[hh] = stt[8 + 4 * g + hh];
        }
#pragma unroll
        for (int i = 0; i < 4; i++) {
            int n = ty * 4 + i;
            float g0v = sg0[n], g1v = sg1[n];
#pragma unroll
            for (int j = 0; j < 2; j++) {
                int p = i * 2 + j, m = tx + 16 * j;
                int i0 = i0r[p]; float fr = frr[p];
                float4 ta = __ldg((const float4*)&g_tbl[i0 * 8 + 4 * g]);
                float4 tb = __ldg((const float4*)&g_tbl[(i0 + 1) * 8 + 4 * g]);
                float geo[4];
                geo[0] = ta.x + fr * (tb.x - ta.x);
                geo[1] = ta.y + fr * (tb.y - ta.y);
                geo[2] = ta.z + fr * (tb.z - ta.z);
                geo[3] = ta.w + fr * (tb.w - ta.w);
                int bit = (bitm >> p) & 1;
                int base = ((n0 + n) * 8 + 4 * g) * 1024 + m0 + m;
#pragma unroll
                for (int hh = 0; hh < 4; hh++) {
                    float bias = g0v * geo[hh] + g1v * (bit ? tt1[hh] : tt0[hh]);
                    g_logits[base + hh * 1024] = fmaf(res[hh][i][j], scale, bias);
                }
            }
        }
    }
}

// ---------------- row stats (max, 1/sum of exp) -------------------------------
__global__ __launch_bounds__(256) void stats_kernel() {
    int row = blockIdx.x;
    const float* p = g_logits + (long)row * 1024;
    int tid = threadIdx.x;
    float4 v = *(const float4*)&p[tid * 4];
    float mx = fmaxf(fmaxf(v.x, v.y), fmaxf(v.z, v.w));
    for (int o = 16; o; o >>= 1) mx = fmaxf(mx, __shfl_xor_sync(~0u, mx, o));
    __shared__ float rm[8], rs[8];
    if ((tid & 31) == 0) rm[tid >> 5] = mx;
    __syncthreads();
    mx = rm[0];
#pragma unroll
    for (int j = 1; j < 8; j++) mx = fmaxf(mx, rm[j]);
    float s = __expf(v.x - mx) + __expf(v.y - mx) + __expf(v.z - mx) + __expf(v.w - mx);
    for (int o = 16; o; o >>= 1) s += __shfl_xor_sync(~0u, s, o);
    if ((tid & 31) == 0) rs[tid >> 5] = s;
    __syncthreads();
    if (tid == 0) {
        float tot = 0.f;
#pragma unroll
        for (int j = 0; j < 8; j++) tot += rs[j];
        g_stats[row] = make_float2(mx, __fdividef(1.f, tot));
    }
}

// -------- PV with inline softmax, 32-row blocks (256-block grid) -------------
__global__ __launch_bounds__(256) void pv_kernel() {
    int h = blockIdx.x, n0 = blockIdx.y * 32;
    __shared__ float As[32][36];   // n x m (softmaxed probs)
    __shared__ float Bs[32][32];   // m x d
    __shared__ float2 sstat[32];
    int tid = threadIdx.x;
    int dxi = tid & 31;
    int ty = tid >> 5;
    if (tid < 32) sstat[tid] = g_stats[(n0 + tid) * 8 + h];
    __syncthreads();
    float acc[4];
#pragma unroll
    for (int i = 0; i < 4; i++) acc[i] = 0.f;

    for (int m0 = 0; m0 < 1024; m0 += 32) {
        {
            int r = tid >> 3, c4 = (tid & 7) << 2;
            float4 v = *(const float4*)&g_logits[((long)(n0 + r) * 8 + h) * 1024 + m0 + c4];
            float2 st = sstat[r];
            v.x = __expf(v.x - st.x) * st.y;
            v.y = __expf(v.y - st.x) * st.y;
            v.z = __expf(v.z - st.x) * st.y;
            v.w = __expf(v.w - st.x) * st.y;
            *(float4*)&As[r][c4] = v;
            *(float4*)&Bs[r][c4] = *(const float4*)&g_v[(m0 + r) * 256 + h * 32 + c4];
        }
        __syncthreads();
#pragma unroll
        for (int mm = 0; mm < 32; mm += 4) {
            float b0 = Bs[mm + 0][dxi], b1 = Bs[mm + 1][dxi];
            float b2 = Bs[mm + 2][dxi], b3 = Bs[mm + 3][dxi];
#pragma unroll
            for (int i = 0; i < 4; i++) {
                float4 a = *(const float4*)&As[ty + 8 * i][mm];
                acc[i] = fmaf(a.x, b0, fmaf(a.y, b1, fmaf(a.z, b2, fmaf(a.w, b3, acc[i]))));
            }
        }
        __syncthreads();
    }
#pragma unroll
    for (int i = 0; i < 4; i++)
        g_attnout[(n0 + ty + 8 * i) * 256 + h * 32 + dxi] = acc[i];
}

// ---------------- residual + layernorm ----------------------------------------
__global__ __launch_bounds__(256) void ln_kernel(const float* __restrict__ src,
                                                 const float* __restrict__ g,
                                                 const float* __restrict__ b,
                                                 float* __restrict__ out) {
    int n = blockIdx.x, tid = threadIdx.x;
    float x = src[n * 256 + tid] + g_proj[n * 256 + tid];
    float s = x;
    for (int o = 16; o; o >>= 1) s += __shfl_xor_sync(~0u, s, o);
    __shared__ float r1[8], r2[8];
    if ((tid & 31) == 0) r1[tid >> 5] = s;
    __syncthreads();
    float tot = 0.f;
#pragma unroll
    for (int j = 0; j < 8; j++) tot += r1[j];
    float mu = tot * (1.f / 256.f);
    float d = x - mu;
    float s2 = d * d;
    for (int o = 16; o; o >>= 1) s2 += __shfl_xor_sync(~0u, s2, o);
    if ((tid & 31) == 0) r2[tid >> 5] = s2;
    __syncthreads();
    float var = 0.f;
#pragma unroll
    for (int j = 0; j < 8; j++) var += r2[j];
    var *= (1.f / 256.f);
    out[n * 256 + tid] = d * rsqrtf(var + 1e-5f) * g[tid] + b[tid];
}

// ---------------- launch ------------------------------------------------------
extern "C" void kernel_launch(void* const* d_in, const int* in_sizes, int n_in,
                              void* d_out, int out_size) {
    const float* src_feat = (const float*)d_in[0];
    const float* tgt_feat = (const float*)d_in[1];
    const float* src_pos  = (const float*)d_in[2];
    const void*  edges    = d_in[3];
    const float* Wq = (const float*)d_in[4],  *bq = (const float*)d_in[5];
    const float* Wk = (const float*)d_in[6],  *bk = (const float*)d_in[7];
    const float* Wv = (const float*)d_in[8],  *bv = (const float*)d_in[9];
    const float* geo_w1 = (const float*)d_in[10], *geo_b1 = (const float*)d_in[11];
    const float* geo_w2 = (const float*)d_in[12], *geo_b2 = (const float*)d_in[13];
    const float* top_w1 = (const float*)d_in[14], *top_b1 = (const float*)d_in[15];
    const float* top_w2 = (const float*)d_in[16], *top_b2 = (const float*)d_in[17];
    const float* gate_w1 = (const float*)d_in[18], *gate_b1 = (const float*)d_in[19];
    const float* gate_w2 = (const float*)d_in[20], *gate_b2 = (const float*)d_in[21];
    const float* Wo = (const float*)d_in[22], *bo = (const float*)d_in[23];
    const float* ln_g = (const float*)d_in[24], *ln_b = (const float*)d_in[25];
    float* out = (float*)d_out;

    void *pgateh, *pattn, *pproj;
    cudaGetSymbolAddress(&pgateh, g_gateh);
    cudaGetSymbolAddress(&pattn, g_attnout);
    cudaGetSymbolAddress(&pproj, g_proj);

    cudaFuncSetAttribute(logits_kernel,
                         cudaFuncAttributeMaxDynamicSharedMemorySize, LOGITS_SMEM);

    // 1: geo table + zero adj + ttab (fused setup)
    setup_kernel<<<33, 256>>>(geo_w1, geo_b1, geo_w2, geo_b2,
                              top_w1, top_b1, top_w2, top_b2);
    // 2: scatter edges (inline dtype detect)
    scatter_edges_kernel<<<64, 256>>>((const unsigned*)edges);
    // 3: path round 1
    path_round_kernel<<<128, 256>>>(0);
    // 4: gate MLP GEMM (positioned for ncu capture): 1024x1024, K=512, 256 blocks
    sgemm64<<<dim3(16, 16), 256>>>(src_feat, tgt_feat, 256, 256, gate_w1, 1024,
                                   gate_b1, (float*)pgateh, 1024, 512, 1);
    // 5-6: path rounds 2,3 (final path in g_pa)
    path_round_kernel<<<128, 256>>>(1);
    path_round_kernel<<<128, 256>>>(2);
    // 7: q/k/v projections (192 blocks)
    qkv_kernel<<<dim3(4, 16, 3), 256>>>(src_feat, tgt_feat, Wq, bq, Wk, bk, Wv, bv);
    // 8: gate head + 2-way softmax
    gate2_kernel<<<1024, 256>>>(gate_w2, gate_b2);
    // 9-11: fused logits (512 blocks), row stats, PV (256 blocks)
    logits_kernel<<<dim3(32, 16), 256, LOGITS_SMEM>>>(src_pos);
    stats_kernel<<<8192, 256>>>();
    pv_kernel<<<dim3(8, 32), 256>>>();
    // 12: output projection
    sgemm64<<<dim3(4, 16), 256>>>((const float*)pattn, (const float*)pattn, 256, 256,
                                  Wo, 256, bo, (float*)pproj, 256, 256, 0);
    // 13: residual + layernorm
    ln_kernel<<<1024, 256>>>(src_feat, ln_g, ln_b, out);
}

// round 17
// speedup vs baseline: 1.0258x; 1.0258x over previous
#include <cuda_runtime.h>
#include <cuda_bf16.h>

#define NN 1024
#define HID 256
#define NH 8
#define HD 32
#define NE 16384

#define TBL_N 8192
#define TBL_MAX 24.0f
#define TBL_SCALE ((float)(TBL_N - 1) / TBL_MAX)

typedef unsigned long long ull;

// ---- packed fp32x2 helpers (sm_103a FFMA2) ----------------------------------
__device__ __forceinline__ ull pack2(float lo, float hi) {
    ull r; asm("mov.b64 %0, {%1, %2};" : "=l"(r) : "f"(lo), "f"(hi)); return r;
}
__device__ __forceinline__ float2 unpack2(ull v) {
    float2 f; asm("mov.b64 {%0, %1}, %2;" : "=f"(f.x), "=f"(f.y) : "l"(v)); return f;
}
__device__ __forceinline__ void fma2(ull& d, ull a, ull b) {
    asm("fma.rn.f32x2 %0, %1, %2, %0;" : "+l"(d) : "l"(a), "l"(b));
}

// ---------------- scratch (static device memory; no allocations) -------------
__device__ float    g_q[NN * HID];
__device__ float    g_k[NN * HID];
__device__ float    g_v[NN * HID];
__device__ float    g_gate[NN * 2];              // raw gate logit sums (atomic)
__device__ unsigned g_adj[NN * 32];
__device__ unsigned g_pa[NN * 32];
__device__ unsigned g_pb[NN * 32];
__device__ float    g_ttab[16];                  // [path_val(0/1)][head]
__device__ float    g_tbl[TBL_N * 8];            // geo MLP lookup table [i][h]
__device__ float    g_logits[NN * NH * NN];      // 32 MB, [n][h][m], raw logits
__device__ float2   g_pstat[NN * NH * 32];       // per (row, mblock) partial (max, sumexp)
__device__ float2   g_stats[NN * NH];            // per-row (max, 1/sum)
__device__ float    g_attnout[NN * HID];
__device__ float    g_proj[NN * HID];

// - setup: geo table (blocks 0-31) + zero adj slices; block 32: ttab + zero gate
__global__ void setup_kernel(const float* __restrict__ gw1, const float* __restrict__ gb1,
                             const float* __restrict__ gw2, const float* __restrict__ gb2,
                             const float* __restrict__ tw1, const float* __restrict__ tb1,
                             const float* __restrict__ tw2, const float* __restrict__ tb2) {
    int b = blockIdx.x, tid = threadIdx.x;
    if (b < 32) {
#pragma unroll
        for (int t = 0; t < 4; t++) g_adj[b * 1024 + tid + 256 * t] = 0u;
        int i = b * 256 + tid;
        float dist = (float)i * (TBL_MAX / (float)(TBL_N - 1));
        float a[8];
#pragma unroll
        for (int h = 0; h < 8; h++) a[h] = gb2[h];
        for (int c = 0; c < 32; c++) {
            float hv = fmaf(dist, gw1[c], gb1[c]);
            float s = __fdividef(hv, 1.f + __expf(-hv));
#pragma unroll
            for (int h = 0; h < 8; h++) a[h] = fmaf(s, gw2[c * 8 + h], a[h]);
        }
#pragma unroll
        for (int h = 0; h < 8; h++) g_tbl[i * 8 + h] = a[h];
    } else {
#pragma unroll
        for (int t = 0; t < 8; t++) g_gate[tid + 256 * t] = 0.f;
        if (tid < 16) {
            float pv = (float)(tid >> 3);
            int h = tid & 7;
            float acc = tb2[h];
            for (int c = 0; c < 32; c++) {
                float hv = fmaf(pv, tw1[c], tb1[c]);
                float s = __fdividef(hv, 1.f + __expf(-hv));
                acc = fmaf(s, tw2[c * 8 + h], acc);
            }
            g_ttab[tid] = acc;
        }
    }
}

// ---------------- scatter edges with inline dtype detect ----------------------
__global__ void scatter_edges_kernel(const unsigned* __restrict__ w) {
    bool is64 = true;
#pragma unroll
    for (int i = 1; i < 16; i += 2) is64 &= (w[i] == 0u);
    int e = blockIdx.x * blockDim.x + threadIdx.x;
    if (e >= NE) return;
    int s, d;
    if (is64) {
        const long long* p = (const long long*)w;
        s = (int)p[e];
        d = (int)p[NE + e];
    } else {
        const int* p = (const int*)w;
        s = p[e];
        d = p[NE + e];
    }
    atomicOr(&g_adj[s * 32 + (d >> 5)], 1u << (d & 31));
}

// path = min(path, path @ adj): binary reachability step on bitsets.
#define LIST_CAP 512
__global__ __launch_bounds__(256) void path_round_kernel(int r) {
    const unsigned* in = (r == 0) ? g_adj : ((r == 1) ? g_pa : g_pb);
    unsigned* out = (r == 1) ? g_pb : g_pa;
    __shared__ unsigned short lists[8][LIST_CAP];
    int warp = threadIdx.x >> 5, lane = threadIdx.x & 31;
    int row = blockIdx.x * 8 + warp;
    unsigned w = in[row * 32 + lane];
    int c = __popc(w);
    int pre = c;
#pragma unroll
    for (int o = 1; o < 32; o <<= 1) {
        int x = __shfl_up_sync(~0u, pre, o);
        if (lane >= o) pre += x;
    }
    int total = __shfl_sync(~0u, pre, 31);
    unsigned acc = 0u;
    if (total <= LIST_CAP) {
        int k = pre - c;
        unsigned tmp = w;
        while (tmp) {
            int b = __ffs(tmp) - 1; tmp &= tmp - 1;
            lists[warp][k++] = (unsigned short)(lane * 32 + b);
        }
        __syncwarp();
        int j = 0;
        for (; j + 8 <= total; j += 8) {
            unsigned a0 = g_adj[lists[warp][j + 0] * 32 + lane];
            unsigned a1 = g_adj[lists[warp][j + 1] * 32 + lane];
            unsigned a2 = g_adj[lists[warp][j + 2] * 32 + lane];
            unsigned a3 = g_adj[lists[warp][j + 3] * 32 + lane];
            unsigned a4 = g_adj[lists[warp][j + 4] * 32 + lane];
            unsigned a5 = g_adj[lists[warp][j + 5] * 32 + lane];
            unsigned a6 = g_adj[lists[warp][j + 6] * 32 + lane];
            unsigned a7 = g_adj[lists[warp][j + 7] * 32 + lane];
            acc |= (a0 | a1) | (a2 | a3) | (a4 | a5) | (a6 | a7);
        }
        for (; j < total; j++) acc |= g_adj[lists[warp][j] * 32 + lane];
    } else {
        for (int ww = 0; ww < 32; ww++) {
            unsigned word = __shfl_sync(~0u, w, ww);
            while (word) {
                int b = __ffs(word) - 1; word &= word - 1;
                acc |= g_adj[(ww * 32 + b) * 32 + lane];
            }
        }
    }
    out[row * 32 + lane] = w & acc;
}

// ---- 64x64 tiled SGEMM body, double-buffered, FFMA2 row pairs ---------------
// C = [A0|A1] @ B + bias [, silu].
// gate mode (gate_out != nullptr): instead of storing C, reduce
// silu(v) . w2 per row and atomically accumulate the 2 gate logits.
__device__ __forceinline__ void gemm_body(
    const float* __restrict__ A0, const float* __restrict__ A1, int ksplit,
    int lda, const float* __restrict__ B, int ldb,
    const float* __restrict__ bias, float* __restrict__ C, int ldc, int K, int act,
    const float* __restrict__ w2, float* __restrict__ gate_out)
{
    __shared__ float As[2][16][68];
    __shared__ float Bs[2][16][64];
    int tid = threadIdx.x;
    int tx = tid & 15, ty = tid >> 4;
    int row0 = blockIdx.y * 64, col0 = blockIdx.x * 64;
    ull acc2[2][4];
#pragma unroll
    for (int p = 0; p < 2; p++)
#pragma unroll
        for (int j = 0; j < 4; j++) acc2[p][j] = 0ull;
    int ar = tid >> 2, ac = (tid & 3) << 2;
    int bk = tid >> 4, bn = (tid & 15) << 2;

    {
        const float* Ap = (0 < ksplit)
            ? &A0[(row0 + ar) * lda + ac]
            : &A1[(row0 + ar) * lda + ac];
        float4 av = *(const float4*)Ap;
        As[0][ac + 0][ar] = av.x; As[0][ac + 1][ar] = av.y;
        As[0][ac + 2][ar] = av.z; As[0][ac + 3][ar] = av.w;
        *(float4*)&Bs[0][bk][bn] = *(const float4*)&B[bk * ldb + col0 + bn];
    }
    __syncthreads();

    int cur = 0;
    for (int k0 = 0; k0 < K; k0 += 16) {
        int nxt = cur ^ 1;
        bool has_next = (k0 + 16 < K);
        float4 av, bv;
        if (has_next) {
            int k1 = k0 + 16;
            const float* Ap = (k1 < ksplit)
                ? &A0[(row0 + ar) * lda + k1 + ac]
                : &A1[(row0 + ar) * lda + (k1 - ksplit) + ac];
            av = *(const float4*)Ap;
            bv = *(const float4*)&B[(k1 + bk) * ldb + col0 + bn];
        }
#pragma unroll
        for (int kk = 0; kk < 16; kk++) {
            ulonglong2 ap = *(const ulonglong2*)&As[cur][kk][ty << 2];
            float4 b = *(const float4*)&Bs[cur][kk][tx << 2];
            ull bb0 = pack2(b.x, b.x), bb1 = pack2(b.y, b.y);
            ull bb2 = pack2(b.z, b.z), bb3 = pack2(b.w, b.w);
            fma2(acc2[0][0], ap.x, bb0); fma2(acc2[0][1], ap.x, bb1);
            fma2(acc2[0][2], ap.x, bb2); fma2(acc2[0][3], ap.x, bb3);
            fma2(acc2[1][0], ap.y, bb0); fma2(acc2[1][1], ap.y, bb1);
            fma2(acc2[1][2], ap.y, bb2); fma2(acc2[1][3], ap.y, bb3);
        }
        if (has_next) {
            As[nxt][ac + 0][ar] = av.x; As[nxt][ac + 1][ar] = av.y;
            As[nxt][ac + 2][ar] = av.z; As[nxt][ac + 3][ar] = av.w;
            *(float4*)&Bs[nxt][bk][bn] = bv;
            __syncthreads();
        }
        cur = nxt;
    }

    if (gate_out == nullptr) {
#pragma unroll
        for (int p = 0; p < 2; p++) {
            int r = row0 + (ty << 2) + (p << 1);
#pragma unroll
            for (int j = 0; j < 4; j++) {
                int cc = col0 + (tx << 2) + j;
                float2 v = unpack2(acc2[p][j]);
                float v0 = v.x + bias[cc];
                float v1 = v.y + bias[cc];
                if (act) {
                    v0 = __fdividef(v0, 1.f + __expf(-v0));
                    v1 = __fdividef(v1, 1.f + __expf(-v1));
                }
                C[r * ldc + cc] = v0;
                C[(r + 1) * ldc + cc] = v1;
            }
        }
    } else {
        // gate mode: silu then partial dot with w2, half-warp reduce, atomics
        float rs0[4] = {0.f, 0.f, 0.f, 0.f};
        float rs1[4] = {0.f, 0.f, 0.f, 0.f};
#pragma unroll
        for (int p = 0; p < 2; p++) {
#pragma unroll
            for (int j = 0; j < 4; j++) {
                int cc = col0 + (tx << 2) + j;
                float2 v = unpack2(acc2[p][j]);
                float v0 = v.x + bias[cc];
                float v1 = v.y + bias[cc];
                v0 = __fdividef(v0, 1.f + __expf(-v0));
                v1 = __fdividef(v1, 1.f + __expf(-v1));
                float w20 = w2[cc * 2 + 0], w21 = w2[cc * 2 + 1];
                rs0[(p << 1) + 0] = fmaf(v0, w20, rs0[(p << 1) + 0]);
                rs1[(p << 1) + 0] = fmaf(v0, w21, rs1[(p << 1) + 0]);
                rs0[(p << 1) + 1] = fmaf(v1, w20, rs0[(p << 1) + 1]);
                rs1[(p << 1) + 1] = fmaf(v1, w21, rs1[(p << 1) + 1]);
            }
        }
        // reduce over the 16 tx lanes (same half-warp, same rows)
#pragma unroll
        for (int l = 0; l < 4; l++) {
#pragma unroll
            for (int o = 1; o < 16; o <<= 1) {
                rs0[l] += __shfl_xor_sync(~0u, rs0[l], o);
                rs1[l] += __shfl_xor_sync(~0u, rs1[l], o);
            }
        }
        if (tx == 0) {
#pragma unroll
            for (int l = 0; l < 4; l++) {
                int r = row0 + (ty << 2) + l;
                atomicAdd(&gate_out[r * 2 + 0], rs0[l]);
                atomicAdd(&gate_out[r * 2 + 1], rs1[l]);
            }
        }
    }
}

__global__ __launch_bounds__(256) void sgemm64(
    const float* __restrict__ A0, const float* __restrict__ A1, int ksplit,
    int lda, const float* __restrict__ B, int ldb,
    const float* __restrict__ bias, float* __restrict__ C, int ldc, int K, int act,
    const float* __restrict__ w2, float* __restrict__ gate_out)
{
    gemm_body(A0, A1, ksplit, lda, B, ldb, bias, C, ldc, K, act, w2, gate_out);
}

// q/k/v projections fused via blockIdx.z
__global__ __launch_bounds__(256) void qkv_kernel(
    const float* __restrict__ src, const float* __restrict__ tgt,
    const float* __restrict__ Wq, const float* __restrict__ bq,
    const float* __restrict__ Wk, const float* __restrict__ bk,
    const float* __restrict__ Wv, const float* __restrict__ bv)
{
    int z = blockIdx.z;
    const float* A = (z == 0) ? src : tgt;
    const float* W = (z == 0) ? Wq : ((z == 1) ? Wk : Wv);
    const float* b = (z == 0) ? bq : ((z == 1) ? bk : bv);
    float* C = (z == 0) ? g_q : ((z == 1) ? g_k : g_v);
    gemm_body(A, A, 256, 256, W, 256, b, C, 256, 256, 0, nullptr, nullptr);
}

// ======== logits: 64n x 32m tile, thread = 4n x 2m x 4h, 2 head-groups =======
// Also emits per-(row, mblock) partial softmax stats to g_pstat.
#define LQ_QS   0                       // [64][132]
#define LQ_KS   8448                    // [32][132]
#define LQ_SPN  12672                   // 192
#define LQ_SPM  12864                   // 96
#define LQ_SG0  12960                   // 64
#define LQ_SG1  13024                   // 64
#define LQ_STT  13088                   // 16
#define LQ_SPW  13104                   // 64 (unsigned)
#define LOGITS_SMEM ((13104 + 64) * 4)

__global__ __launch_bounds__(256) void logits_kernel(const float* __restrict__ pos,
                                                     const float* __restrict__ gate_b2)
{
    extern __shared__ float sh[];
    float* qs = sh + LQ_QS;
    float* ks = sh + LQ_KS;
    float* spn = sh + LQ_SPN;
    float* spm = sh + LQ_SPM;
    float* sg0 = sh + LQ_SG0;
    float* sg1 = sh + LQ_SG1;
    float* stt = sh + LQ_STT;
    unsigned* spw = (unsigned*)(sh + LQ_SPW);

    int tid = threadIdx.x;
    int tx = tid & 15, ty = tid >> 4;
    int mb = blockIdx.x;
    int m0 = mb * 32, n0 = blockIdx.y * 64;
    const float scale = 0.17677669529663687f;   // 1/sqrt(32)

    if (tid < 192) spn[tid] = pos[n0 * 3 + tid];
    if (tid < 96)  spm[tid] = pos[m0 * 3 + tid];
    if (tid < 64) {
        // raw gate sums -> 2-way softmax inline
        float l0 = g_gate[(n0 + tid) * 2 + 0] + gate_b2[0];
        float l1 = g_gate[(n0 + tid) * 2 + 1] + gate_b2[1];
        float mm = fmaxf(l0, l1);
        float e0 = __expf(l0 - mm), e1 = __expf(l1 - mm);
        float inv = __fdividef(1.f, e0 + e1);
        sg0[tid] = e0 * inv;
        sg1[tid] = e1 * inv;
        spw[tid] = g_pa[(n0 + tid) * 32 + mb];
    }
    if (tid < 16) stt[tid] = g_ttab[tid];
    __syncthreads();

    int i0r[8]; float frr[8]; unsigned bitm = 0;
#pragma unroll
    for (int i = 0; i < 4; i++) {
        int n = ty * 4 + i;
        float pnx = spn[n * 3 + 0], pny = spn[n * 3 + 1], pnz = spn[n * 3 + 2];
#pragma unroll
        for (int j = 0; j < 2; j++) {
            int m = tx + 16 * j;
            float dx = pnx - spm[m * 3 + 0];
            float dy = pny - spm[m * 3 + 1];
            float dz = pnz - spm[m * 3 + 2];
            float dist = sqrtf(fmaxf(dx * dx + dy * dy + dz * dz, 1e-12f));
            float t = fminf(dist, TBL_MAX) * TBL_SCALE;
            int i0 = (int)t;
            if (i0 > TBL_N - 2) i0 = TBL_N - 2;
            int p = i * 2 + j;
            i0r[p] = i0;
            frr[p] = t - (float)i0;
            bitm |= ((spw[n] >> m) & 1u) << p;
        }
    }

    for (int g = 0; g < 2; g++) {
        __syncthreads();
        for (int l = tid; l < 2048; l += 256) {
            int r = l >> 5, c4 = (l & 31) << 2;
            *(float4*)&qs[r * 132 + c4] =
                *(const float4*)&g_q[(n0 + r) * 256 + g * 128 + c4];
        }
        for (int l = tid; l < 1024; l += 256) {
            int r = l >> 5, c4 = (l & 31) << 2;
            *(float4*)&ks[r * 132 + c4] =
                *(const float4*)&g_k[(m0 + r) * 256 + g * 128 + c4];
        }
        __syncthreads();

        float res[4][4][2];
#pragma unroll
        for (int hh = 0; hh < 4; hh++)
#pragma unroll
            for (int i = 0; i < 4; i++) { res[hh][i][0] = 0.f; res[hh][i][1] = 0.f; }

#pragma unroll
        for (int dd = 0; dd < 128; dd += 4) {
            const int hh = dd >> 5;
            float4 qv[4], kv[2];
#pragma unroll
            for (int i = 0; i < 4; i++)
                qv[i] = *(const float4*)&qs[(ty * 4 + i) * 132 + dd];
            kv[0] = *(const float4*)&ks[tx * 132 + dd];
            kv[1] = *(const float4*)&ks[(tx + 16) * 132 + dd];
#pragma unroll
            for (int i = 0; i < 4; i++) {
#pragma unroll
                for (int j = 0; j < 2; j++) {
                    res[hh][i][j] = fmaf(qv[i].x, kv[j].x,
                                    fmaf(qv[i].y, kv[j].y,
                                    fmaf(qv[i].z, kv[j].z,
                                    fmaf(qv[i].w, kv[j].w, res[hh][i][j]))));
                }
            }
        }

        float tt0[4], tt1[4];
#pragma unroll
        for (int hh = 0; hh < 4; hh++) {
            tt0[hh] = stt[4 * g + hh];
            tt1[hh] = stt[8 + 4 * g + hh];
        }
        // finalize logits (bias + scale), store, keep in res
#pragma unroll
        for (int i = 0; i < 4; i++) {
            int n = ty * 4 + i;
            float g0v = sg0[n], g1v = sg1[n];
#pragma unroll
            for (int j = 0; j < 2; j++) {
                int p = i * 2 + j, m = tx + 16 * j;
                int i0 = i0r[p]; float fr = frr[p];
                float4 ta = __ldg((const float4*)&g_tbl[i0 * 8 + 4 * g]);
                float4 tb = __ldg((const float4*)&g_tbl[(i0 + 1) * 8 + 4 * g]);
                float geo[4];
                geo[0] = ta.x + fr * (tb.x - ta.x);
                geo[1] = ta.y + fr * (tb.y - ta.y);
                geo[2] = ta.z + fr * (tb.z - ta.z);
                geo[3] = ta.w + fr * (tb.w - ta.w);
                int bit = (bitm >> p) & 1;
                int base = ((n0 + n) * 8 + 4 * g) * 1024 + m0 + m;
#pragma unroll
                for (int hh = 0; hh < 4; hh++) {
                    float bias = g0v * geo[hh] + g1v * (bit ? tt1[hh] : tt0[hh]);
                    float lv = fmaf(res[hh][i][j], scale, bias);
                    res[hh][i][j] = lv;
                    g_logits[base + hh * 1024] = lv;
                }
            }
        }
        // partial stats per (n, h) row over this 32-m chunk (half-warp owns row)
#pragma unroll
        for (int i = 0; i < 4; i++) {
#pragma unroll
            for (int hh = 0; hh < 4; hh++) {
                float va = res[hh][i][0], vb = res[hh][i][1];
                float lm = fmaxf(va, vb);
                lm = fmaxf(lm, __shfl_xor_sync(~0u, lm, 1));
                lm = fmaxf(lm, __shfl_xor_sync(~0u, lm, 2));
                lm = fmaxf(lm, __shfl_xor_sync(~0u, lm, 4));
                lm = fmaxf(lm, __shfl_xor_sync(~0u, lm, 8));
                float s = __expf(va - lm) + __expf(vb - lm);
                s += __shfl_xor_sync(~0u, s, 1);
                s += __shfl_xor_sync(~0u, s, 2);
                s += __shfl_xor_sync(~0u, s, 4);
                s += __shfl_xor_sync(~0u, s, 8);
                if (tx == 0) {
                    int row = (n0 + ty * 4 + i) * 8 + 4 * g + hh;
                    g_pstat[row * 32 + mb] = make_float2(lm, s);
                }
            }
        }
    }
}

// ---------------- combine partial stats: 32 partials -> (max, 1/sum) ---------
__global__ __launch_bounds__(256) void combine_kernel() {
    int warp = threadIdx.x >> 5, lane = threadIdx.x & 31;
    int row = blockIdx.x * 8 + warp;
    float2 ps = g_pstat[row * 32 + lane];
    float M = ps.x;
#pragma unroll
    for (int o = 16; o; o >>= 1) M = fmaxf(M, __shfl_xor_sync(~0u, M, o));
    float S = ps.y * __expf(ps.x - M);
#pragma unroll
    for (int o = 16; o; o >>= 1) S += __shfl_xor_sync(~0u, S, o);
    if (lane == 0) g_stats[row] = make_float2(M, __fdividef(1.f, S));
}

// -------- PV with inline softmax, 32-row blocks (256-block grid) -------------
__global__ __launch_bounds__(256) void pv_kernel() {
    int h = blockIdx.x, n0 = blockIdx.y * 32;
    __shared__ float As[32][36];   // n x m (softmaxed probs)
    __shared__ float Bs[32][32];   // m x d
    __shared__ float2 sstat[32];
    int tid = threadIdx.x;
    int dxi = tid & 31;
    int ty = tid >> 5;
    if (tid < 32) sstat[tid] = g_stats[(n0 + tid) * 8 + h];
    __syncthreads();
    float acc[4];
#pragma unroll
    for (int i = 0; i < 4; i++) acc[i] = 0.f;

    for (int m0 = 0; m0 < 1024; m0 += 32) {
        {
            int r = tid >> 3, c4 = (tid & 7) << 2;
            float4 v = *(const float4*)&g_logits[((long)(n0 + r) * 8 + h) * 1024 + m0 + c4];
            float2 st = sstat[r];
            v.x = __expf(v.x - st.x) * st.y;
            v.y = __expf(v.y - st.x) * st.y;
            v.z = __expf(v.z - st.x) * st.y;
            v.w = __expf(v.w - st.x) * st.y;
            *(float4*)&As[r][c4] = v;
            *(float4*)&Bs[r][c4] = *(const float4*)&g_v[(m0 + r) * 256 + h * 32 + c4];
        }
        __syncthreads();
#pragma unroll
        for (int mm = 0; mm < 32; mm += 4) {
            float b0 = Bs[mm + 0][dxi], b1 = Bs[mm + 1][dxi];
            float b2 = Bs[mm + 2][dxi], b3 = Bs[mm + 3][dxi];
#pragma unroll
            for (int i = 0; i < 4; i++) {
                float4 a = *(const float4*)&As[ty + 8 * i][mm];
                acc[i] = fmaf(a.x, b0, fmaf(a.y, b1, fmaf(a.z, b2, fmaf(a.w, b3, acc[i]))));
            }
        }
        __syncthreads();
    }
#pragma unroll
    for (int i = 0; i < 4; i++)
        g_attnout[(n0 + ty + 8 * i) * 256 + h * 32 + dxi] = acc[i];
}

// ---------------- residual + layernorm ----------------------------------------
__global__ __launch_bounds__(256) void ln_kernel(const float* __restrict__ src,
                                                 const float* __restrict__ g,
                                                 const float* __restrict__ b,
                                                 float* __restrict__ out) {
    int n = blockIdx.x, tid = threadIdx.x;
    float x = src[n * 256 + tid] + g_proj[n * 256 + tid];
    float s = x;
    for (int o = 16; o; o >>= 1) s += __shfl_xor_sync(~0u, s, o);
    __shared__ float r1[8], r2[8];
    if ((tid & 31) == 0) r1[tid >> 5] = s;
    __syncthreads();
    float tot = 0.f;
#pragma unroll
    for (int j = 0; j < 8; j++) tot += r1[j];
    float mu = tot * (1.f / 256.f);
    float d = x - mu;
    float s2 = d * d;
    for (int o = 16; o; o >>= 1) s2 += __shfl_xor_sync(~0u, s2, o);
    if ((tid & 31) == 0) r2[tid >> 5] = s2;
    __syncthreads();
    float var = 0.f;
#pragma unroll
    for (int j = 0; j < 8; j++) var += r2[j];
    var *= (1.f / 256.f);
    out[n * 256 + tid] = d * rsqrtf(var + 1e-5f) * g[tid] + b[tid];
}

// ---------------- launch ------------------------------------------------------
extern "C" void kernel_launch(void* const* d_in, const int* in_sizes, int n_in,
                              void* d_out, int out_size) {
    const float* src_feat = (const float*)d_in[0];
    const float* tgt_feat = (const float*)d_in[1];
    const float* src_pos  = (const float*)d_in[2];
    const void*  edges    = d_in[3];
    const float* Wq = (const float*)d_in[4],  *bq = (const float*)d_in[5];
    const float* Wk = (const float*)d_in[6],  *bk = (const float*)d_in[7];
    const float* Wv = (const float*)d_in[8],  *bv = (const float*)d_in[9];
    const float* geo_w1 = (const float*)d_in[10], *geo_b1 = (const float*)d_in[11];
    const float* geo_w2 = (const float*)d_in[12], *geo_b2 = (const float*)d_in[13];
    const float* top_w1 = (const float*)d_in[14], *top_b1 = (const float*)d_in[15];
    const float* top_w2 = (const float*)d_in[16], *top_b2 = (const float*)d_in[17];
    const float* gate_w1 = (const float*)d_in[18], *gate_b1 = (const float*)d_in[19];
    const float* gate_w2 = (const float*)d_in[20], *gate_b2 = (const float*)d_in[21];
    const float* Wo = (const float*)d_in[22], *bo = (const float*)d_in[23];
    const float* ln_g = (const float*)d_in[24], *ln_b = (const float*)d_in[25];
    float* out = (float*)d_out;

    void *pattn, *pproj, *pgate;
    cudaGetSymbolAddress(&pattn, g_attnout);
    cudaGetSymbolAddress(&pproj, g_proj);
    cudaGetSymbolAddress(&pgate, g_gate);

    cudaFuncSetAttribute(logits_kernel,
                         cudaFuncAttributeMaxDynamicSharedMemorySize, LOGITS_SMEM);

    // 1: geo table + zero adj + ttab + zero gate accumulators
    setup_kernel<<<33, 256>>>(geo_w1, geo_b1, geo_w2, geo_b2,
                              top_w1, top_b1, top_w2, top_b2);
    // 2: scatter edges (inline dtype detect)
    scatter_edges_kernel<<<64, 256>>>((const unsigned*)edges);
    // 3: path round 1
    path_round_kernel<<<128, 256>>>(0);
    // 4: gate MLP GEMM with fused gate-head reduction (no C store)
    sgemm64<<<dim3(16, 16), 256>>>(src_feat, tgt_feat, 256, 256, gate_w1, 1024,
                                   gate_b1, nullptr, 0, 512, 1,
                                   gate_w2, (float*)pgate);
    // 5-6: path rounds 2,3 (final path in g_pa)
    path_round_kernel<<<128, 256>>>(1);
    path_round_kernel<<<128, 256>>>(2);
    // 7: q/k/v projections (192 blocks)
    qkv_kernel<<<dim3(4, 16, 3), 256>>>(src_feat, tgt_feat, Wq, bq, Wk, bk, Wv, bv);
    // 8: fused logits (512 blocks) + partial softmax stats; inline gate softmax
    logits_kernel<<<dim3(32, 16), 256, LOGITS_SMEM>>>(src_pos, gate_b2);
    // 9: combine partial stats (1024 blocks)
    combine_kernel<<<1024, 256>>>();
    // 10: PV (256 blocks)
    pv_kernel<<<dim3(8, 32), 256>>>();
    // 11: output projection
    sgemm64<<<dim3(4, 16), 256>>>((const float*)pattn, (const float*)pattn, 256, 256,
                                  Wo, 256, bo, (float*)pproj, 256, 256, 0,
                                  nullptr, nullptr);
    // 12: residual + layernorm
    ln_kernel<<<1024, 256>>>(src_feat, ln_g, ln_b, out);
}